// round 2
// baseline (speedup 1.0000x reference)
#include <cuda_runtime.h>
#include <cstdint>

#define N_NODES   50000
#define IN_FEAT   64
#define HIDDEN    128
#define N_EDGES   800000
#define NUM_LAYERS 3

// ---------------- scratch (device globals; no allocation allowed) ----------
__device__ __align__(128) float g_hA [N_NODES * HIDDEN];
__device__ __align__(128) float g_hB [N_NODES * HIDDEN];
__device__ __align__(128) float g_t  [N_NODES * HIDDEN];
__device__ __align__(128) float g_agg[N_NODES * HIDDEN];
__device__ int g_cnt[N_NODES];
__device__ int g_is64;   // 1 if edge_index is int64, 0 if int32

// ---------------- helpers ---------------------------------------------------
__device__ __forceinline__ void red_add_v4(float* addr, float4 v) {
    asm volatile("red.global.add.v4.f32 [%0], {%1,%2,%3,%4};"
                 :: "l"(addr), "f"(v.x), "f"(v.y), "f"(v.z), "f"(v.w)
                 : "memory");
}

// index e of the src row (row 0) / dst row (row 1) of edge_index
__device__ __forceinline__ int load_src(const int* ei, int e, int is64) {
    return is64 ? ei[2 * e] : ei[e];
}
__device__ __forceinline__ int load_dst(const int* ei, int e, int is64) {
    return is64 ? ei[2 * (N_EDGES + e)] : ei[N_EDGES + e];
}

// ---------------- dtype detect ----------------------------------------------
// If int64 with values < 2^31, every odd 32-bit word is 0.
__global__ void detect_k(const int* __restrict__ ei) {
    int ok = 1;
#pragma unroll 8
    for (int i = 0; i < 128; i++)
        if (ei[2 * i + 1] != 0) { ok = 0; break; }
    g_is64 = ok;
}

// ---------------- zero kernels ----------------------------------------------
__global__ void zero4_k(float4* __restrict__ p, int n4) {
    int i = blockIdx.x * blockDim.x + threadIdx.x;
    if (i < n4) p[i] = make_float4(0.f, 0.f, 0.f, 0.f);
}

__global__ void zero_int_k(int* __restrict__ p, int n) {
    int i = blockIdx.x * blockDim.x + threadIdx.x;
    if (i < n) p[i] = 0;
}

// ---------------- degree count ----------------------------------------------
__global__ void count_k(const int* __restrict__ ei) {
    int e = blockIdx.x * blockDim.x + threadIdx.x;
    if (e >= N_EDGES) return;
    int d = load_dst(ei, e, g_is64);
    atomicAdd(&g_cnt[d], 1);
}

// ---------------- scatter: agg[dst] += t[src] --------------------------------
// one warp per edge, each lane handles a float4 (32 lanes * 16B = 512B row)
__global__ void scatter_k(const float* __restrict__ t,
                          const int* __restrict__ ei) {
    int gtid = blockIdx.x * blockDim.x + threadIdx.x;
    int e = gtid >> 5;
    if (e >= N_EDGES) return;
    int is64 = g_is64;
    int c = (gtid & 31) * 4;
    int s = load_src(ei, e, is64);
    int d = load_dst(ei, e, is64);
    float4 v = *(const float4*)(t + (size_t)s * HIDDEN + c);
    red_add_v4(g_agg + (size_t)d * HIDDEN + c, v);
}

// ---------------- tiled GEMM: C[M x 128] = A[M x K] @ W[K x 128] -------------
// MODE 0: C = A@W
// MODE 1: C = A@W + bias
// MODE 2: C = elu(A@W + bias + agg/max(cnt,1))
template <int K, int MODE>
__global__ __launch_bounds__(256)
void gemm128_k(const float* __restrict__ A,
               const float* __restrict__ W,
               const float* __restrict__ bias,
               const float* __restrict__ agg,
               const int*   __restrict__ cnt,
               float* __restrict__ C,
               int M) {
    constexpr int BM = 64, BN = 128, BK = 16;
    __shared__ float As[BK][BM];
    __shared__ float Bs[BK][BN];

    const int tid = threadIdx.x;
    const int block_row = blockIdx.x * BM;
    const int tx = tid & 31;   // 32 column groups of TN=4
    const int ty = tid >> 5;   // 8 row groups of TM=8

    float acc[8][4];
#pragma unroll
    for (int i = 0; i < 8; i++)
#pragma unroll
        for (int j = 0; j < 4; j++) acc[i][j] = 0.f;

    const int arow = tid >> 2;        // 0..63
    const int acol = (tid & 3) * 4;   // 0,4,8,12

    for (int k0 = 0; k0 < K; k0 += BK) {
        // load A tile (64 x 16), transposed into shared
        int grow = block_row + arow;
        float4 av = make_float4(0.f, 0.f, 0.f, 0.f);
        if (grow < M)
            av = *(const float4*)(A + (size_t)grow * K + k0 + acol);
        As[acol + 0][arow] = av.x;
        As[acol + 1][arow] = av.y;
        As[acol + 2][arow] = av.z;
        As[acol + 3][arow] = av.w;

        // load B tile (16 x 128): 512 float4, 2 per thread
#pragma unroll
        for (int r = 0; r < 2; r++) {
            int idx  = tid + r * 256;     // float4 index
            int brow = idx >> 5;
            int bcol = (idx & 31) * 4;
            float4 bv = *(const float4*)(W + (size_t)(k0 + brow) * BN + bcol);
            *(float4*)&Bs[brow][bcol] = bv;
        }
        __syncthreads();

#pragma unroll
        for (int k = 0; k < BK; k++) {
            float a[8];
            float4 a0 = *(const float4*)&As[k][ty * 8];
            float4 a1 = *(const float4*)&As[k][ty * 8 + 4];
            a[0] = a0.x; a[1] = a0.y; a[2] = a0.z; a[3] = a0.w;
            a[4] = a1.x; a[5] = a1.y; a[6] = a1.z; a[7] = a1.w;
            float4 bv = *(const float4*)&Bs[k][tx * 4];
            float b[4] = {bv.x, bv.y, bv.z, bv.w};
#pragma unroll
            for (int i = 0; i < 8; i++)
#pragma unroll
                for (int j = 0; j < 4; j++)
                    acc[i][j] = fmaf(a[i], b[j], acc[i][j]);
        }
        __syncthreads();
    }

    // epilogue
    const int col = tx * 4;
    float4 bv = make_float4(0.f, 0.f, 0.f, 0.f);
    if (MODE >= 1) bv = *(const float4*)(bias + col);

#pragma unroll
    for (int i = 0; i < 8; i++) {
        int row = block_row + ty * 8 + i;
        if (row >= M) continue;
        float v[4] = {acc[i][0], acc[i][1], acc[i][2], acc[i][3]};
        if (MODE >= 1) { v[0] += bv.x; v[1] += bv.y; v[2] += bv.z; v[3] += bv.w; }
        if (MODE == 2) {
            float invc = 1.0f / fmaxf((float)cnt[row], 1.0f);
            float4 av = *(const float4*)(agg + (size_t)row * HIDDEN + col);
            v[0] += av.x * invc; v[1] += av.y * invc;
            v[2] += av.z * invc; v[3] += av.w * invc;
#pragma unroll
            for (int j = 0; j < 4; j++)
                v[j] = (v[j] > 0.f) ? v[j] : expm1f(v[j]);
        }
        *(float4*)(C + (size_t)row * HIDDEN + col) =
            make_float4(v[0], v[1], v[2], v[3]);
    }
}

// ---------------- launch ------------------------------------------------------
extern "C" void kernel_launch(void* const* d_in, const int* in_sizes, int n_in,
                              void* d_out, int out_size) {
    const float* x      = (const float*)d_in[0];
    const int*   ei     = (const int*)d_in[1];   // int32 or int64, auto-detected
    const float* W_in   = (const float*)d_in[2];
    const float* b_in   = (const float*)d_in[3];
    const float* W_self = (const float*)d_in[4];
    const float* b_self = (const float*)d_in[5];
    const float* W_nbr  = (const float*)d_in[6];
    float*       out    = (float*)d_out;

    float* hA;  cudaGetSymbolAddress((void**)&hA,  g_hA);
    float* hB;  cudaGetSymbolAddress((void**)&hB,  g_hB);
    float* t;   cudaGetSymbolAddress((void**)&t,   g_t);
    float* agg; cudaGetSymbolAddress((void**)&agg, g_agg);
    int*   cnt; cudaGetSymbolAddress((void**)&cnt, g_cnt);

    const int M = N_NODES;
    const int gemm_blocks = (M + 63) / 64;
    const int n4 = N_NODES * HIDDEN / 4;

    // dtype detect + degree counts (once per call)
    detect_k<<<1, 1>>>(ei);
    zero_int_k<<<(N_NODES + 255) / 256, 256>>>(cnt, N_NODES);
    count_k<<<(N_EDGES + 255) / 256, 256>>>(ei);

    // input projection: hA = x @ W_in + b_in
    gemm128_k<IN_FEAT, 1><<<gemm_blocks, 256>>>(x, W_in, b_in, nullptr, nullptr, hA, M);

    const float* hcur = hA;
    for (int l = 0; l < NUM_LAYERS; l++) {
        const float* Wn = W_nbr  + (size_t)l * HIDDEN * HIDDEN;
        const float* Ws = W_self + (size_t)l * HIDDEN * HIDDEN;
        const float* bs = b_self + (size_t)l * HIDDEN;
        float* hnext = (l == NUM_LAYERS - 1) ? out : ((hcur == hA) ? hB : hA);

        // t = hcur @ W_nbr[l]
        gemm128_k<HIDDEN, 0><<<gemm_blocks, 256>>>(hcur, Wn, nullptr, nullptr, nullptr, t, M);
        // agg = 0
        zero4_k<<<(n4 + 255) / 256, 256>>>((float4*)agg, n4);
        // agg[dst] += t[src]
        scatter_k<<<(N_EDGES * 32 + 255) / 256, 256>>>(t, ei);
        // hnext = elu(hcur @ W_self[l] + b_self[l] + agg/cnt)
        gemm128_k<HIDDEN, 2><<<gemm_blocks, 256>>>(hcur, Ws, bs, agg, cnt, hnext, M);

        hcur = hnext;
    }
}

// round 3
// speedup vs baseline: 1.1035x; 1.1035x over previous
#include <cuda_runtime.h>
#include <cstdint>

#define N_NODES   50000
#define IN_FEAT   64
#define HIDDEN    128
#define N_EDGES   800000
#define NUM_LAYERS 3

// ---------------- scratch (device globals; no allocation allowed) ----------
__device__ __align__(128) float g_hA [N_NODES * HIDDEN];
__device__ __align__(128) float g_hB [N_NODES * HIDDEN];
__device__ __align__(128) float g_t  [N_NODES * HIDDEN];
__device__ __align__(128) float g_z  [N_NODES * HIDDEN];
__device__ int g_cnt   [N_NODES];
__device__ int g_offs  [N_NODES + 1];
__device__ int g_cursor[N_NODES];
__device__ int g_esrc  [N_EDGES];
__device__ int g_is64;   // 1 if edge_index is int64, 0 if int32

// ---------------- index helpers --------------------------------------------
__device__ __forceinline__ int load_src(const int* ei, int e, int is64) {
    return is64 ? ei[2 * e] : ei[e];
}
__device__ __forceinline__ int load_dst(const int* ei, int e, int is64) {
    return is64 ? ei[2 * (N_EDGES + e)] : ei[N_EDGES + e];
}

// ---------------- dtype detect ----------------------------------------------
// If int64 with values < 2^31, every odd 32-bit word is 0.
__global__ void detect_k(const int* __restrict__ ei) {
    int lane = threadIdx.x;
    int bad = 0;
    for (int i = lane; i < 256; i += 32) bad |= (ei[2 * i + 1] != 0);
    bad = __any_sync(0xFFFFFFFFu, bad);
    if (lane == 0) g_is64 = !bad;
}

// ---------------- zero / count ------------------------------------------------
__global__ void zero_int_k(int* __restrict__ p, int n) {
    int i = blockIdx.x * blockDim.x + threadIdx.x;
    if (i < n) p[i] = 0;
}

__global__ void count_k(const int* __restrict__ ei) {
    int e = blockIdx.x * blockDim.x + threadIdx.x;
    if (e >= N_EDGES) return;
    atomicAdd(&g_cnt[load_dst(ei, e, g_is64)], 1);
}

// ---------------- single-block exclusive scan (50000 elems) -------------------
__global__ __launch_bounds__(1024)
void scan_k() {
    constexpr int CHUNK = (N_NODES + 1023) / 1024;  // 49
    __shared__ int warp_sums[32];
    int t    = threadIdx.x;
    int lane = t & 31;
    int wid  = t >> 5;
    int base = t * CHUNK;

    // local sum
    int s = 0;
    for (int i = 0; i < CHUNK; i++) {
        int idx = base + i;
        if (idx < N_NODES) s += g_cnt[idx];
    }
    int local = s;

    // warp inclusive scan
    int inc = s;
    for (int d = 1; d < 32; d <<= 1) {
        int n = __shfl_up_sync(0xFFFFFFFFu, inc, d);
        if (lane >= d) inc += n;
    }
    if (lane == 31) warp_sums[wid] = inc;
    __syncthreads();
    if (wid == 0) {
        int v = warp_sums[lane];
        for (int d = 1; d < 32; d <<= 1) {
            int n = __shfl_up_sync(0xFFFFFFFFu, v, d);
            if (lane >= d) v += n;
        }
        warp_sums[lane] = v;   // inclusive warp prefix
    }
    __syncthreads();

    int prefix = inc - local + (wid > 0 ? warp_sums[wid - 1] : 0);

    // write offsets + cursor
    int run = prefix;
    for (int i = 0; i < CHUNK; i++) {
        int idx = base + i;
        if (idx < N_NODES) {
            g_offs[idx]   = run;
            g_cursor[idx] = run;
            run += g_cnt[idx];
        }
    }
    // the thread whose chunk contains the last element writes the total
    if (base <= N_NODES - 1 && N_NODES - 1 < base + CHUNK)
        g_offs[N_NODES] = run;
}

// ---------------- CSR fill -----------------------------------------------------
__global__ void fill_k(const int* __restrict__ ei) {
    int e = blockIdx.x * blockDim.x + threadIdx.x;
    if (e >= N_EDGES) return;
    int is64 = g_is64;
    int s = load_src(ei, e, is64);
    int d = load_dst(ei, e, is64);
    int pos = atomicAdd(&g_cursor[d], 1);
    g_esrc[pos] = s;
}

// ---------------- fused gather + epilogue --------------------------------------
// out[n] = elu( z[n] + (sum_{e in CSR[n]} t[src_e]) / max(deg,1) )
__global__ __launch_bounds__(256)
void gather_fused_k(const float* __restrict__ t,
                    const float* __restrict__ z,
                    float* __restrict__ out) {
    int gtid = blockIdx.x * blockDim.x + threadIdx.x;
    int node = gtid >> 5;
    if (node >= N_NODES) return;
    int lane = gtid & 31;
    int c = lane * 4;

    int start = g_offs[node];
    int end   = g_offs[node + 1];

    float4 acc = make_float4(0.f, 0.f, 0.f, 0.f);
    int e = start;
    for (; e + 4 <= end; e += 4) {
        int s0 = g_esrc[e + 0];
        int s1 = g_esrc[e + 1];
        int s2 = g_esrc[e + 2];
        int s3 = g_esrc[e + 3];
        float4 v0 = __ldg((const float4*)(t + (size_t)s0 * HIDDEN + c));
        float4 v1 = __ldg((const float4*)(t + (size_t)s1 * HIDDEN + c));
        float4 v2 = __ldg((const float4*)(t + (size_t)s2 * HIDDEN + c));
        float4 v3 = __ldg((const float4*)(t + (size_t)s3 * HIDDEN + c));
        acc.x += v0.x + v1.x + v2.x + v3.x;
        acc.y += v0.y + v1.y + v2.y + v3.y;
        acc.z += v0.z + v1.z + v2.z + v3.z;
        acc.w += v0.w + v1.w + v2.w + v3.w;
    }
    for (; e < end; e++) {
        int s = g_esrc[e];
        float4 v = __ldg((const float4*)(t + (size_t)s * HIDDEN + c));
        acc.x += v.x; acc.y += v.y; acc.z += v.z; acc.w += v.w;
    }

    float inv = 1.0f / fmaxf((float)(end - start), 1.0f);
    float4 zv = __ldg((const float4*)(z + (size_t)node * HIDDEN + c));
    float4 r;
    r.x = zv.x + acc.x * inv;
    r.y = zv.y + acc.y * inv;
    r.z = zv.z + acc.z * inv;
    r.w = zv.w + acc.w * inv;
    r.x = (r.x > 0.f) ? r.x : expm1f(r.x);
    r.y = (r.y > 0.f) ? r.y : expm1f(r.y);
    r.z = (r.z > 0.f) ? r.z : expm1f(r.z);
    r.w = (r.w > 0.f) ? r.w : expm1f(r.w);
    *(float4*)(out + (size_t)node * HIDDEN + c) = r;
}

// ---------------- tiled GEMM: C[M x 128] = A[M x K] @ W[K x 128] ---------------
// BM=128, BN=128, BK=16, 256 threads, 8x8 per thread.
// MODE 0: C = A@W        MODE 1: C = A@W + bias
template <int K, int MODE>
__global__ __launch_bounds__(256, 2)
void gemm128_k(const float* __restrict__ A,
               const float* __restrict__ W,
               const float* __restrict__ bias,
               float* __restrict__ C,
               int M) {
    constexpr int BM = 128, BN = 128, BK = 16;
    __shared__ float As[BK][BM];   // transposed A tile
    __shared__ float Bs[BK][BN];

    const int tid = threadIdx.x;
    const int block_row = blockIdx.x * BM;
    const int tx = tid & 15;   // 16 column groups of 8
    const int ty = tid >> 4;   // 16 row groups of 8

    float acc[8][8];
#pragma unroll
    for (int i = 0; i < 8; i++)
#pragma unroll
        for (int j = 0; j < 8; j++) acc[i][j] = 0.f;

    const int arow = tid >> 1;          // 0..127
    const int acol = (tid & 1) * 8;     // 0 or 8

    for (int k0 = 0; k0 < K; k0 += BK) {
        // A tile: 128 rows x 16 cols, each thread loads 8 consecutive floats
        {
            int grow = block_row + arow;
            float4 av0 = make_float4(0.f, 0.f, 0.f, 0.f);
            float4 av1 = make_float4(0.f, 0.f, 0.f, 0.f);
            if (grow < M) {
                av0 = *(const float4*)(A + (size_t)grow * K + k0 + acol);
                av1 = *(const float4*)(A + (size_t)grow * K + k0 + acol + 4);
            }
            As[acol + 0][arow] = av0.x;
            As[acol + 1][arow] = av0.y;
            As[acol + 2][arow] = av0.z;
            As[acol + 3][arow] = av0.w;
            As[acol + 4][arow] = av1.x;
            As[acol + 5][arow] = av1.y;
            As[acol + 6][arow] = av1.z;
            As[acol + 7][arow] = av1.w;
        }
        // B tile: 16 x 128, 2 float4 per thread
#pragma unroll
        for (int r = 0; r < 2; r++) {
            int idx  = tid + r * 256;
            int brow = idx >> 5;
            int bcol = (idx & 31) * 4;
            *(float4*)&Bs[brow][bcol] =
                *(const float4*)(W + (size_t)(k0 + brow) * BN + bcol);
        }
        __syncthreads();

#pragma unroll
        for (int k = 0; k < BK; k++) {
            float a[8], b[8];
            float4 a0 = *(const float4*)&As[k][ty * 8];
            float4 a1 = *(const float4*)&As[k][ty * 8 + 4];
            a[0] = a0.x; a[1] = a0.y; a[2] = a0.z; a[3] = a0.w;
            a[4] = a1.x; a[5] = a1.y; a[6] = a1.z; a[7] = a1.w;
            float4 b0 = *(const float4*)&Bs[k][tx * 8];
            float4 b1 = *(const float4*)&Bs[k][tx * 8 + 4];
            b[0] = b0.x; b[1] = b0.y; b[2] = b0.z; b[3] = b0.w;
            b[4] = b1.x; b[5] = b1.y; b[6] = b1.z; b[7] = b1.w;
#pragma unroll
            for (int i = 0; i < 8; i++)
#pragma unroll
                for (int j = 0; j < 8; j++)
                    acc[i][j] = fmaf(a[i], b[j], acc[i][j]);
        }
        __syncthreads();
    }

    // epilogue
    const int col = tx * 8;
    float bv[8] = {0, 0, 0, 0, 0, 0, 0, 0};
    if (MODE == 1) {
        float4 b0 = *(const float4*)(bias + col);
        float4 b1 = *(const float4*)(bias + col + 4);
        bv[0] = b0.x; bv[1] = b0.y; bv[2] = b0.z; bv[3] = b0.w;
        bv[4] = b1.x; bv[5] = b1.y; bv[6] = b1.z; bv[7] = b1.w;
    }

#pragma unroll
    for (int i = 0; i < 8; i++) {
        int row = block_row + ty * 8 + i;
        if (row >= M) continue;
        float v[8];
#pragma unroll
        for (int j = 0; j < 8; j++) v[j] = acc[i][j] + bv[j];
        *(float4*)(C + (size_t)row * HIDDEN + col) =
            make_float4(v[0], v[1], v[2], v[3]);
        *(float4*)(C + (size_t)row * HIDDEN + col + 4) =
            make_float4(v[4], v[5], v[6], v[7]);
    }
}

// ---------------- launch ---------------------------------------------------------
extern "C" void kernel_launch(void* const* d_in, const int* in_sizes, int n_in,
                              void* d_out, int out_size) {
    const float* x      = (const float*)d_in[0];
    const int*   ei     = (const int*)d_in[1];   // int32 or int64, auto-detected
    const float* W_in   = (const float*)d_in[2];
    const float* b_in   = (const float*)d_in[3];
    const float* W_self = (const float*)d_in[4];
    const float* b_self = (const float*)d_in[5];
    const float* W_nbr  = (const float*)d_in[6];
    float*       out    = (float*)d_out;

    float* hA; cudaGetSymbolAddress((void**)&hA, g_hA);
    float* hB; cudaGetSymbolAddress((void**)&hB, g_hB);
    float* t;  cudaGetSymbolAddress((void**)&t,  g_t);
    float* z;  cudaGetSymbolAddress((void**)&z,  g_z);
    int*   cnt; cudaGetSymbolAddress((void**)&cnt, g_cnt);

    const int M = N_NODES;
    const int gemm_blocks = (M + 127) / 128;

    // ---- CSR build (per call; inputs identical each replay) ----
    detect_k<<<1, 32>>>(ei);
    zero_int_k<<<(N_NODES + 255) / 256, 256>>>(cnt, N_NODES);
    count_k<<<(N_EDGES + 255) / 256, 256>>>(ei);
    scan_k<<<1, 1024>>>();
    fill_k<<<(N_EDGES + 255) / 256, 256>>>(ei);

    // ---- input projection: hA = x @ W_in + b_in ----
    gemm128_k<IN_FEAT, 1><<<gemm_blocks, 256>>>(x, W_in, b_in, hA, M);

    const float* hcur = hA;
    for (int l = 0; l < NUM_LAYERS; l++) {
        const float* Wn = W_nbr  + (size_t)l * HIDDEN * HIDDEN;
        const float* Ws = W_self + (size_t)l * HIDDEN * HIDDEN;
        const float* bs = b_self + (size_t)l * HIDDEN;
        float* hnext = (l == NUM_LAYERS - 1) ? out : ((hcur == hA) ? hB : hA);

        // t = hcur @ W_nbr[l]
        gemm128_k<HIDDEN, 0><<<gemm_blocks, 256>>>(hcur, Wn, nullptr, t, M);
        // z = hcur @ W_self[l] + b_self[l]
        gemm128_k<HIDDEN, 1><<<gemm_blocks, 256>>>(hcur, Ws, bs, z, M);
        // hnext = elu(z + gather(t)/deg)
        gather_fused_k<<<(N_NODES * 32 + 255) / 256, 256>>>(t, z, hnext);

        hcur = hnext;
    }
}

// round 5
// speedup vs baseline: 2.0679x; 1.8740x over previous
#include <cuda_runtime.h>
#include <cuda_bf16.h>
#include <cstdint>

#define N_NODES   50000
#define IN_FEAT   64
#define HIDDEN    128
#define N_EDGES   800000
#define NUM_LAYERS 3
#define NBLK      ((N_NODES + 255) / 256)   // 196

// ---------------- scratch (device globals; no allocation allowed) ------------
__device__ __align__(128) float g_hA [N_NODES * HIDDEN];
__device__ __align__(128) float g_hB [N_NODES * HIDDEN];
__device__ __align__(128) float g_t  [N_NODES * HIDDEN];
__device__ __align__(128) float g_z  [N_NODES * HIDDEN];
__device__ int g_cnt   [N_NODES];
__device__ int g_offs  [N_NODES + 1];
__device__ int g_cursor[N_NODES];
__device__ int g_esrc  [N_EDGES];
__device__ int g_bsum  [NBLK];
__device__ int g_is64;
// pre-converted weights, fragment-major bf16 hi/lo; slot stride 32 KB
__device__ __align__(256) uint32_t g_whi[7 * 8192];
__device__ __align__(256) uint32_t g_wlo[7 * 8192];

// ---------------- bf16 split helpers -----------------------------------------
// pack two floats (low = x, high = y) into bf16x2
__device__ __forceinline__ uint32_t pack_bf16x2(float x, float y) {
    uint32_t r;
    asm("cvt.rn.bf16x2.f32 %0, %1, %2;" : "=r"(r) : "f"(y), "f"(x));
    return r;
}
// split float2 -> (hi bf16x2, lo bf16x2 residual)
__device__ __forceinline__ void split2(float2 v, uint32_t& hi, uint32_t& lo) {
    hi = pack_bf16x2(v.x, v.y);
    float hx = __uint_as_float(hi << 16);
    float hy = __uint_as_float(hi & 0xFFFF0000u);
    lo = pack_bf16x2(v.x - hx, v.y - hy);
}

__device__ __forceinline__ void mma_bf16(float* c, const uint32_t* a, uint32_t b0, uint32_t b1) {
    asm volatile(
        "mma.sync.aligned.m16n8k16.row.col.f32.bf16.bf16.f32 "
        "{%0,%1,%2,%3}, {%4,%5,%6,%7}, {%8,%9}, {%0,%1,%2,%3};"
        : "+f"(c[0]), "+f"(c[1]), "+f"(c[2]), "+f"(c[3])
        : "r"(a[0]), "r"(a[1]), "r"(a[2]), "r"(a[3]), "r"(b0), "r"(b1));
}

// ---------------- index helpers ----------------------------------------------
__device__ __forceinline__ int load_src(const int* ei, int e, int is64) {
    return is64 ? ei[2 * e] : ei[e];
}
__device__ __forceinline__ int load_dst(const int* ei, int e, int is64) {
    return is64 ? ei[2 * (N_EDGES + e)] : ei[N_EDGES + e];
}

// ---------------- dtype detect -------------------------------------------------
__global__ void detect_k(const int* __restrict__ ei) {
    int lane = threadIdx.x;
    int bad = 0;
    for (int i = lane; i < 256; i += 32) bad |= (ei[2 * i + 1] != 0);
    bad = __any_sync(0xFFFFFFFFu, bad);
    if (lane == 0) g_is64 = !bad;
}

// ---------------- zero / count --------------------------------------------------
__global__ void zero_int_k(int* __restrict__ p, int n) {
    int i = blockIdx.x * blockDim.x + threadIdx.x;
    if (i < n) p[i] = 0;
}
__global__ void count_k(const int* __restrict__ ei) {
    int e = blockIdx.x * blockDim.x + threadIdx.x;
    if (e >= N_EDGES) return;
    atomicAdd(&g_cnt[load_dst(ei, e, g_is64)], 1);
}

// ---------------- 3-phase scan ----------------------------------------------------
__global__ __launch_bounds__(256) void scan1_k() {
    __shared__ int ws[8];
    int idx = blockIdx.x * 256 + threadIdx.x;
    int v = (idx < N_NODES) ? g_cnt[idx] : 0;
    int lane = threadIdx.x & 31, wid = threadIdx.x >> 5;
    for (int d = 16; d > 0; d >>= 1) v += __shfl_down_sync(0xFFFFFFFFu, v, d);
    if (lane == 0) ws[wid] = v;
    __syncthreads();
    if (threadIdx.x == 0) {
        int s = 0;
        for (int i = 0; i < 8; i++) s += ws[i];
        g_bsum[blockIdx.x] = s;
    }
}
__global__ __launch_bounds__(256) void scan2_k() {
    __shared__ int sh[256];
    int t = threadIdx.x;
    int v = (t < NBLK) ? g_bsum[t] : 0;
    sh[t] = v;
    __syncthreads();
    for (int d = 1; d < 256; d <<= 1) {
        int n = (t >= d) ? sh[t - d] : 0;
        __syncthreads();
        sh[t] += n;
        __syncthreads();
    }
    if (t < NBLK) g_bsum[t] = sh[t] - v;   // exclusive prefix
}
__global__ __launch_bounds__(256) void scan3_k() {
    __shared__ int sh[256];
    int t = threadIdx.x;
    int idx = blockIdx.x * 256 + t;
    int v = (idx < N_NODES) ? g_cnt[idx] : 0;
    sh[t] = v;
    __syncthreads();
    for (int d = 1; d < 256; d <<= 1) {
        int n = (t >= d) ? sh[t - d] : 0;
        __syncthreads();
        sh[t] += n;
        __syncthreads();
    }
    int ex = g_bsum[blockIdx.x] + sh[t] - v;
    if (idx < N_NODES) {
        g_offs[idx]   = ex;
        g_cursor[idx] = ex;
        if (idx == N_NODES - 1) g_offs[N_NODES] = ex + v;
    }
}

// ---------------- CSR fill --------------------------------------------------------
__global__ void fill_k(const int* __restrict__ ei) {
    int e = blockIdx.x * blockDim.x + threadIdx.x;
    if (e >= N_EDGES) return;
    int is64 = g_is64;
    int s = load_src(ei, e, is64);
    int d = load_dst(ei, e, is64);
    g_esrc[atomicAdd(&g_cursor[d], 1)] = s;
}

// ---------------- weight convert: W[K_,128] -> fragment-major bf16 hi/lo ----------
// word index: ((J * NSTEP + s) * 32 + lane) * 2 + r
//   J = n-tile (0..15), s = k-step, lane: t=lane&3, g=lane>>2, r = k-half
//   b-reg holds W[k][n], W[k+1][n] packed (low = k), k = s*16 + t*2 + r*8, n = J*8 + g
__global__ void conv_w_k(const float* __restrict__ W, int K_, int slot) {
    uint32_t* hi = g_whi + slot * 8192;
    uint32_t* lo = g_wlo + slot * 8192;
    int NSTEP = K_ / 16;
    int total = 16 * NSTEP * 64;
    for (int idx = blockIdx.x * blockDim.x + threadIdx.x; idx < total;
         idx += gridDim.x * blockDim.x) {
        int J = idx / (NSTEP * 64);
        int rem = idx % (NSTEP * 64);
        int s = rem / 64;
        int rem2 = rem % 64;
        int l = rem2 >> 1, r = rem2 & 1;
        int t = l & 3, g = l >> 2;
        int k = s * 16 + t * 2 + r * 8;
        int n = J * 8 + g;
        float v0 = W[(size_t)k * HIDDEN + n];
        float v1 = W[(size_t)(k + 1) * HIDDEN + n];
        uint32_t h, lw;
        split2(make_float2(v0, v1), h, lw);
        hi[idx] = h;
        lo[idx] = lw;
    }
}

// ---------------- mma.sync GEMM: C[M x 128] = A[M x K_] @ W + (bias) -----------
// bf16-split 3-pass, fp32 accumulate in registers. No shared memory.
// 256 threads = 8 warps (4 m x 2 n); warp tile 32 x 64.
// MODE 0: C = A@W    MODE 1: C = A@W + bias
template <int K_, int MODE>
__global__ __launch_bounds__(256, 2)
void gemm_mma_k(const float* __restrict__ A, int slot,
                const float* __restrict__ bias,
                float* __restrict__ C, int M) {
    constexpr int NSTEP = K_ / 16;
    const int tid  = threadIdx.x;
    const int warp = tid >> 5;
    const int lane = tid & 31;
    const int g = lane >> 2, t = lane & 3;
    const int warp_m = (warp & 3) * 32;
    const int warp_n = (warp >> 2) * 64;
    const int row_base = blockIdx.x * 128 + warp_m;

    const uint32_t* __restrict__ Bhi = g_whi + slot * 8192;
    const uint32_t* __restrict__ Blo = g_wlo + slot * 8192;

    float acc[2][8][4];
#pragma unroll
    for (int mt = 0; mt < 2; mt++)
#pragma unroll
        for (int j = 0; j < 8; j++)
#pragma unroll
            for (int q = 0; q < 4; q++) acc[mt][j][q] = 0.f;

#pragma unroll
    for (int s = 0; s < NSTEP; s++) {
        uint32_t ahi[2][4], alo[2][4];
        const int c0 = s * 16 + t * 2;
#pragma unroll
        for (int mt = 0; mt < 2; mt++) {
            int r0 = row_base + mt * 16 + g;
            int r1 = r0 + 8;
            float2 v00 = make_float2(0.f, 0.f), v10 = v00, v01 = v00, v11 = v00;
            if (r0 < M) {
                v00 = *(const float2*)(A + (size_t)r0 * K_ + c0);
                v01 = *(const float2*)(A + (size_t)r0 * K_ + c0 + 8);
            }
            if (r1 < M) {
                v10 = *(const float2*)(A + (size_t)r1 * K_ + c0);
                v11 = *(const float2*)(A + (size_t)r1 * K_ + c0 + 8);
            }
            split2(v00, ahi[mt][0], alo[mt][0]);
            split2(v10, ahi[mt][1], alo[mt][1]);
            split2(v01, ahi[mt][2], alo[mt][2]);
            split2(v11, ahi[mt][3], alo[mt][3]);
        }
#pragma unroll
        for (int j = 0; j < 8; j++) {
            int J = (warp >> 2) * 8 + j;
            int w = ((J * NSTEP + s) * 32 + lane) * 2;
            uint32_t b0h = Bhi[w], b1h = Bhi[w + 1];
            uint32_t b0l = Blo[w], b1l = Blo[w + 1];
#pragma unroll
            for (int mt = 0; mt < 2; mt++) {
                mma_bf16(acc[mt][j], ahi[mt], b0h, b1h);
                mma_bf16(acc[mt][j], ahi[mt], b0l, b1l);
                mma_bf16(acc[mt][j], alo[mt], b0h, b1h);
            }
        }
    }

    // epilogue: c0,c1 -> (row g, cols t*2,t*2+1); c2,c3 -> (row g+8)
#pragma unroll
    for (int j = 0; j < 8; j++) {
        int n0 = warp_n + j * 8 + t * 2;
        float2 bv = make_float2(0.f, 0.f);
        if (MODE == 1) bv = *(const float2*)(bias + n0);
#pragma unroll
        for (int mt = 0; mt < 2; mt++) {
            int r0 = row_base + mt * 16 + g;
            int r1 = r0 + 8;
            if (r0 < M)
                *(float2*)(C + (size_t)r0 * HIDDEN + n0) =
                    make_float2(acc[mt][j][0] + bv.x, acc[mt][j][1] + bv.y);
            if (r1 < M)
                *(float2*)(C + (size_t)r1 * HIDDEN + n0) =
                    make_float2(acc[mt][j][2] + bv.x, acc[mt][j][3] + bv.y);
        }
    }
}

// ---------------- fused gather + epilogue -------------------------------------------
__global__ __launch_bounds__(256)
void gather_fused_k(const float* __restrict__ t,
                    const float* __restrict__ z,
                    float* __restrict__ out) {
    int gtid = blockIdx.x * blockDim.x + threadIdx.x;
    int node = gtid >> 5;
    if (node >= N_NODES) return;
    int lane = gtid & 31;
    int c = lane * 4;

    int start = g_offs[node];
    int end   = g_offs[node + 1];

    float4 acc = make_float4(0.f, 0.f, 0.f, 0.f);
    int e = start;
    for (; e + 4 <= end; e += 4) {
        int s0 = g_esrc[e + 0], s1 = g_esrc[e + 1], s2 = g_esrc[e + 2], s3 = g_esrc[e + 3];
        float4 v0 = __ldg((const float4*)(t + (size_t)s0 * HIDDEN + c));
        float4 v1 = __ldg((const float4*)(t + (size_t)s1 * HIDDEN + c));
        float4 v2 = __ldg((const float4*)(t + (size_t)s2 * HIDDEN + c));
        float4 v3 = __ldg((const float4*)(t + (size_t)s3 * HIDDEN + c));
        acc.x += v0.x + v1.x + v2.x + v3.x;
        acc.y += v0.y + v1.y + v2.y + v3.y;
        acc.z += v0.z + v1.z + v2.z + v3.z;
        acc.w += v0.w + v1.w + v2.w + v3.w;
    }
    for (; e < end; e++) {
        int s = g_esrc[e];
        float4 v = __ldg((const float4*)(t + (size_t)s * HIDDEN + c));
        acc.x += v.x; acc.y += v.y; acc.z += v.z; acc.w += v.w;
    }

    float inv = 1.0f / fmaxf((float)(end - start), 1.0f);
    float4 zv = __ldg((const float4*)(z + (size_t)node * HIDDEN + c));
    float4 r;
    r.x = zv.x + acc.x * inv;
    r.y = zv.y + acc.y * inv;
    r.z = zv.z + acc.z * inv;
    r.w = zv.w + acc.w * inv;
    r.x = (r.x > 0.f) ? r.x : expm1f(r.x);
    r.y = (r.y > 0.f) ? r.y : expm1f(r.y);
    r.z = (r.z > 0.f) ? r.z : expm1f(r.z);
    r.w = (r.w > 0.f) ? r.w : expm1f(r.w);
    *(float4*)(out + (size_t)node * HIDDEN + c) = r;
}

// ---------------- launch ----------------------------------------------------------
extern "C" void kernel_launch(void* const* d_in, const int* in_sizes, int n_in,
                              void* d_out, int out_size) {
    const float* x      = (const float*)d_in[0];
    const int*   ei     = (const int*)d_in[1];
    const float* W_in   = (const float*)d_in[2];
    const float* b_in   = (const float*)d_in[3];
    const float* W_self = (const float*)d_in[4];
    const float* b_self = (const float*)d_in[5];
    const float* W_nbr  = (const float*)d_in[6];
    float*       out    = (float*)d_out;

    float* hA; cudaGetSymbolAddress((void**)&hA, g_hA);
    float* hB; cudaGetSymbolAddress((void**)&hB, g_hB);
    float* t;  cudaGetSymbolAddress((void**)&t,  g_t);
    float* z;  cudaGetSymbolAddress((void**)&z,  g_z);
    int*   cnt; cudaGetSymbolAddress((void**)&cnt, g_cnt);

    const int M = N_NODES;
    const int gemm_blocks = (M + 127) / 128;   // 391

    // ---- CSR build ----
    detect_k<<<1, 32>>>(ei);
    zero_int_k<<<(N_NODES + 255) / 256, 256>>>(cnt, N_NODES);
    count_k<<<(N_EDGES + 255) / 256, 256>>>(ei);
    scan1_k<<<NBLK, 256>>>();
    scan2_k<<<1, 256>>>();
    scan3_k<<<NBLK, 256>>>();
    fill_k<<<(N_EDGES + 255) / 256, 256>>>(ei);

    // ---- weight conversion (fragment-major bf16 hi/lo) ----
    conv_w_k<<<32, 256>>>(W_in, 64, 0);
    for (int l = 0; l < NUM_LAYERS; l++) {
        conv_w_k<<<32, 256>>>(W_nbr  + (size_t)l * HIDDEN * HIDDEN, 128, 1 + l);
        conv_w_k<<<32, 256>>>(W_self + (size_t)l * HIDDEN * HIDDEN, 128, 4 + l);
    }

    // ---- input projection: hA = x @ W_in + b_in ----
    gemm_mma_k<IN_FEAT, 1><<<gemm_blocks, 256>>>(x, 0, b_in, hA, M);

    const float* hcur = hA;
    for (int l = 0; l < NUM_LAYERS; l++) {
        const float* bs = b_self + (size_t)l * HIDDEN;
        float* hnext = (l == NUM_LAYERS - 1) ? out : ((hcur == hA) ? hB : hA);

        gemm_mma_k<HIDDEN, 0><<<gemm_blocks, 256>>>(hcur, 1 + l, nullptr, t, M);
        gemm_mma_k<HIDDEN, 1><<<gemm_blocks, 256>>>(hcur, 4 + l, bs, z, M);
        gather_fused_k<<<(N_NODES * 32 + 255) / 256, 256>>>(t, z, hnext);

        hcur = hnext;
    }
}